// round 5
// baseline (speedup 1.0000x reference)
#include <cuda_runtime.h>
#include <cstdint>
#include <math.h>

#define N_NODES 100000
#define N_EDGES 1600000
#define SLAB 12800000               // N_NODES * 128 elements

// ---------------- scratch: ONE pool, 204.8MB + norm + dis = 211.6MB (<256MB!) ----------------
__device__ __align__(16) float g_pool[(size_t)4 * SLAB];
__device__ __align__(16) float g_norm[N_EDGES];
__device__ __align__(16) float g_dis[N_NODES];

// ---------------- Threefry-2x32-20 (exact JAX semantics) ----------------
__host__ __device__ __forceinline__ unsigned rotl32(unsigned x, int r) {
    return (x << r) | (x >> (32 - r));
}

__host__ __device__ __forceinline__ void threefry2x32(unsigned k0, unsigned k1,
                                                      unsigned& x0, unsigned& x1) {
    const unsigned ks2 = k0 ^ k1 ^ 0x1BD11BDAu;
    x0 += k0; x1 += k1;
#define TF_RND(r) { x0 += x1; x1 = rotl32(x1, (r)); x1 ^= x0; }
    TF_RND(13) TF_RND(15) TF_RND(26) TF_RND(6)
    x0 += k1;  x1 += ks2 + 1u;
    TF_RND(17) TF_RND(29) TF_RND(16) TF_RND(24)
    x0 += ks2; x1 += k0 + 2u;
    TF_RND(13) TF_RND(15) TF_RND(26) TF_RND(6)
    x0 += k0;  x1 += k1 + 3u;
    TF_RND(17) TF_RND(29) TF_RND(16) TF_RND(24)
    x0 += k1;  x1 += ks2 + 4u;
    TF_RND(13) TF_RND(15) TF_RND(26) TF_RND(6)
    x0 += ks2; x1 += k0 + 5u;
#undef TF_RND
}

// ---------------- small prep kernels ----------------
__global__ void k_zero_dis() {
    int i = blockIdx.x * 256 + threadIdx.x;
    if (i < N_NODES) g_dis[i] = 0.f;
}

__global__ void k_deg(const int* __restrict__ col) {
    int e = blockIdx.x * 256 + threadIdx.x;
    if (e < N_EDGES) atomicAdd(&g_dis[col[e]], 1.0f);
}

__global__ void k_dis() {
    int i = blockIdx.x * 256 + threadIdx.x;
    if (i < N_NODES) {
        float v = g_dis[i];
        g_dis[i] = (v > 0.f) ? rsqrtf(v) : 0.f;
    }
}

__global__ void k_norm(const int* __restrict__ row, const int* __restrict__ col) {
    int e = blockIdx.x * 256 + threadIdx.x;
    if (e < N_EDGES) g_norm[e] = g_dis[row[e]] * g_dis[col[e]];
}

// ---------------- stacked GEMM: pool[kh*N*out_d + n*out_d + o] = sum_i A[n][i]*W[kh*out_d+o][i]
// BM=128, BN=64, BK=16, TM=8, TN=4, 256 threads. a_off>=0 selects pool as A source.
__global__ void __launch_bounds__(256) k_gemm(const float* __restrict__ Ax,
                                              const float* __restrict__ W,
                                              int a_off, int K, int out_shift) {
    __shared__ float As[16][132];
    __shared__ float Bs[16][68];
    const int tid = threadIdx.x;
    const int n0 = blockIdx.x * 128;
    const int m0 = blockIdx.y * 64;
    const int tx = tid & 15;        // 0..15 -> 4 output cols
    const int ty = tid >> 4;        // 0..15 -> 8 output rows
    const int lr = tid >> 2;        // 0..63 load row
    const int lc = (tid & 3) << 2;  // 0,4,8,12 load k-col

    float acc[8][4] = {};

    for (int k0 = 0; k0 < K; k0 += 16) {
        const int nA0 = n0 + lr;
        const int nA1 = n0 + lr + 64;
        float4 a0 = make_float4(0.f, 0.f, 0.f, 0.f);
        float4 a1 = make_float4(0.f, 0.f, 0.f, 0.f);
        if (a_off >= 0) {
            if (nA0 < N_NODES) a0 = *(const float4*)&g_pool[(size_t)a_off + (size_t)nA0 * K + k0 + lc];
            if (nA1 < N_NODES) a1 = *(const float4*)&g_pool[(size_t)a_off + (size_t)nA1 * K + k0 + lc];
        } else {
            if (nA0 < N_NODES) a0 = *(const float4*)&Ax[(size_t)nA0 * K + k0 + lc];
            if (nA1 < N_NODES) a1 = *(const float4*)&Ax[(size_t)nA1 * K + k0 + lc];
        }
        float4 b = *(const float4*)&W[(size_t)(m0 + lr) * K + k0 + lc];

        As[lc + 0][lr] = a0.x; As[lc + 1][lr] = a0.y; As[lc + 2][lr] = a0.z; As[lc + 3][lr] = a0.w;
        As[lc + 0][lr + 64] = a1.x; As[lc + 1][lr + 64] = a1.y; As[lc + 2][lr + 64] = a1.z; As[lc + 3][lr + 64] = a1.w;
        Bs[lc + 0][lr] = b.x; Bs[lc + 1][lr] = b.y; Bs[lc + 2][lr] = b.z; Bs[lc + 3][lr] = b.w;
        __syncthreads();

#pragma unroll
        for (int kk = 0; kk < 16; kk++) {
            float4 aa0 = *(float4*)&As[kk][ty * 8];
            float4 aa1 = *(float4*)&As[kk][ty * 8 + 4];
            float4 bb  = *(float4*)&Bs[kk][tx * 4];
            float av[8] = {aa0.x, aa0.y, aa0.z, aa0.w, aa1.x, aa1.y, aa1.z, aa1.w};
            float bv[4] = {bb.x, bb.y, bb.z, bb.w};
#pragma unroll
            for (int i = 0; i < 8; i++)
#pragma unroll
                for (int j = 0; j < 4; j++)
                    acc[i][j] = fmaf(av[i], bv[j], acc[i][j]);
        }
        __syncthreads();
    }

    const int out_d = 1 << out_shift;
#pragma unroll
    for (int i = 0; i < 8; i++) {
        const int n = n0 + ty * 8 + i;
        if (n >= N_NODES) continue;
#pragma unroll
        for (int j = 0; j < 4; j++) {
            const int m = m0 + tx * 4 + j;
            const int kh = m >> out_shift;
            const int o = m & (out_d - 1);
            g_pool[(size_t)kh * N_NODES * out_d + (size_t)n * out_d + o] = acc[i][j];
        }
    }
}

// ---------------- SpMM hop (scatter-accumulate): pool[dst + col*d] += norm * pool[src + row*d]
// LANES threads per edge, each handles a float4 (d = 4*LANES)
template <int LANES>
__global__ void __launch_bounds__(256) k_spmm(int src_off, int dst_off,
                                              const int* __restrict__ row,
                                              const int* __restrict__ col) {
    const long long t = (long long)blockIdx.x * 256 + threadIdx.x;
    const int e = (int)(t / LANES);
    const int l = (int)(t % LANES);
    if (e >= N_EDGES) return;
    const int d = LANES * 4;
    const int r = row[e];
    const int c = col[e];
    const float w = g_norm[e];
    const float4 v = *(const float4*)&g_pool[(size_t)src_off + (size_t)r * d + l * 4];
    float* p = &g_pool[(size_t)dst_off + (size_t)c * d + l * 4];
    atomicAdd(p + 0, v.x * w);
    atomicAdd(p + 1, v.y * w);
    atomicAdd(p + 2, v.z * w);
    atomicAdd(p + 3, v.w * w);
}

// ---------------- finalize: bias (+ELU) + exact-JAX dropout; pool -> pool ----------------
__global__ void k_fin_drop(const float* __restrict__ b, int z_off, int h_off,
                           int total, int dmask, unsigned k0, unsigned k1, int do_elu) {
    int i = blockIdx.x * 256 + threadIdx.x;
    if (i >= total) return;
    unsigned x0 = 0u, x1 = (unsigned)i;   // partitionable random_bits: counter (hi,lo)=(0,i)
    threefry2x32(k0, k1, x0, x1);
    const unsigned bits = x0 ^ x1;        // 32-bit output: lane0 ^ lane1
    float v = g_pool[(size_t)z_off + i] + b[i & dmask];
    if (do_elu) v = (v > 0.f) ? v : expm1f(v);
    // keep iff uniform < 0.5 iff top bit clear; kept values scaled by 1/(1-p)=2
    g_pool[(size_t)h_off + i] = (bits & 0x80000000u) ? 0.f : v * 2.0f;
}

__global__ void k_fin_bias(const float* __restrict__ b, float* __restrict__ out,
                           int total, int dmask) {
    int i = blockIdx.x * 256 + threadIdx.x;
    if (i >= total) return;
    out[i] = g_pool[i] + b[i & dmask];
}

// ---------------- driver ----------------
static inline int cdiv(long long a, long long b) { return (int)((a + b - 1) / b); }

extern "C" void kernel_launch(void* const* d_in, const int* in_sizes, int n_in,
                              void* d_out, int out_size) {
    const float* x   = (const float*)d_in[0];
    const int*   ei  = (const int*)d_in[1];      // JAX default: int32 (no x64)
    const float* W1  = (const float*)d_in[2];
    const float* b1  = (const float*)d_in[3];
    const float* W2  = (const float*)d_in[4];
    const float* b2  = (const float*)d_in[5];
    const float* W3  = (const float*)d_in[6];
    const float* b3  = (const float*)d_in[7];
    float*       out = (float*)d_out;

    const int* row = ei;
    const int* col = ei + N_EDGES;

    // dropout keys: dk1, dk2 = split(key(42)); foldlike split -> threefry(key,(0,i)), both lanes
    unsigned dk1a = 0u, dk1b = 0u; threefry2x32(0u, 42u, dk1a, dk1b);   // counter (0,0)
    unsigned dk2a = 0u, dk2b = 1u; threefry2x32(0u, 42u, dk2a, dk2b);   // counter (0,1)

    const int H_OFF = 3 * SLAB;     // h lives in slab 3 (free after the last Horner hop)

    // --- normalization ---
    k_zero_dis<<<cdiv(N_NODES, 256), 256>>>();
    k_deg<<<cdiv(N_EDGES, 256), 256>>>(col);
    k_dis<<<cdiv(N_NODES, 256), 256>>>();
    k_norm<<<cdiv(N_EDGES, 256), 256>>>(row, col);

    // --- Layer 1: in=128, out=128 (shift 7), M=512. z0..z3 = slabs 0..3 (dim 128).
    //     Horner: z2+=A z3; z1+=A z2; z0+=A z1. Then h1 = drop(z0+b1) -> slab 3.
    {
        dim3 g(cdiv(N_NODES, 128), 512 / 64);
        k_gemm<<<g, 256>>>(x, W1, -1, 128, 7);
        const int S = SLAB;
        const long long tot = (long long)N_EDGES * 32;
        k_spmm<32><<<cdiv(tot, 256), 256>>>(3 * S, 2 * S, row, col);
        k_spmm<32><<<cdiv(tot, 256), 256>>>(2 * S, 1 * S, row, col);
        k_spmm<32><<<cdiv(tot, 256), 256>>>(1 * S, 0 * S, row, col);
        k_fin_drop<<<cdiv(N_NODES * 128, 256), 256>>>(b1, 0, H_OFF, N_NODES * 128, 127, dk1a, dk1b, 0);
    }

    // --- Layer 2: in=128 (A at H_OFF), out=64 (shift 6), M=256. z'0..z'3 at 0..3*S (dim 64).
    //     Then h2 = drop(elu(z'0+b2)) -> H_OFF (h1 dead after GEMM).
    {
        dim3 g(cdiv(N_NODES, 128), 256 / 64);
        k_gemm<<<g, 256>>>(nullptr, W2, H_OFF, 128, 6);
        const int S = N_NODES * 64;
        const long long tot = (long long)N_EDGES * 16;
        k_spmm<16><<<cdiv(tot, 256), 256>>>(3 * S, 2 * S, row, col);
        k_spmm<16><<<cdiv(tot, 256), 256>>>(2 * S, 1 * S, row, col);
        k_spmm<16><<<cdiv(tot, 256), 256>>>(1 * S, 0 * S, row, col);
        k_fin_drop<<<cdiv(N_NODES * 64, 256), 256>>>(b2, 0, H_OFF, N_NODES * 64, 63, dk2a, dk2b, 1);
    }

    // --- Layer 3: in=64 (A at H_OFF), out=16 (shift 4), M=64. z''0..z''3 at 0..3*S (dim 16). ---
    {
        dim3 g(cdiv(N_NODES, 128), 64 / 64);
        k_gemm<<<g, 256>>>(nullptr, W3, H_OFF, 64, 4);
        const int S = N_NODES * 16;
        const long long tot = (long long)N_EDGES * 4;
        k_spmm<4><<<cdiv(tot, 256), 256>>>(3 * S, 2 * S, row, col);
        k_spmm<4><<<cdiv(tot, 256), 256>>>(2 * S, 1 * S, row, col);
        k_spmm<4><<<cdiv(tot, 256), 256>>>(1 * S, 0 * S, row, col);
        k_fin_bias<<<cdiv(N_NODES * 16, 256), 256>>>(b3, out, N_NODES * 16, 15);
    }
}

// round 7
// speedup vs baseline: 1.7754x; 1.7754x over previous
#include <cuda_runtime.h>
#include <cstdint>
#include <math.h>

#define N_NODES 100000
#define N_EDGES 1600000
#define SLAB 12800000               // N_NODES * 128 elements

// ---------------- scratch: ONE pool, 204.8MB + norm + deg = 211.6MB (<256MB) ----------------
__device__ __align__(16) float g_pool[(size_t)4 * SLAB];
__device__ __align__(16) float g_norm[N_EDGES];
__device__ __align__(16) float g_deg[N_NODES];

// ---------------- Threefry-2x32-20 (exact JAX semantics) ----------------
__host__ __device__ __forceinline__ unsigned rotl32(unsigned x, int r) {
    return (x << r) | (x >> (32 - r));
}

__host__ __device__ __forceinline__ void threefry2x32(unsigned k0, unsigned k1,
                                                      unsigned& x0, unsigned& x1) {
    const unsigned ks2 = k0 ^ k1 ^ 0x1BD11BDAu;
    x0 += k0; x1 += k1;
#define TF_RND(r) { x0 += x1; x1 = rotl32(x1, (r)); x1 ^= x0; }
    TF_RND(13) TF_RND(15) TF_RND(26) TF_RND(6)
    x0 += k1;  x1 += ks2 + 1u;
    TF_RND(17) TF_RND(29) TF_RND(16) TF_RND(24)
    x0 += ks2; x1 += k0 + 2u;
    TF_RND(13) TF_RND(15) TF_RND(26) TF_RND(6)
    x0 += k0;  x1 += k1 + 3u;
    TF_RND(17) TF_RND(29) TF_RND(16) TF_RND(24)
    x0 += k1;  x1 += ks2 + 4u;
    TF_RND(13) TF_RND(15) TF_RND(26) TF_RND(6)
    x0 += ks2; x1 += k0 + 5u;
#undef TF_RND
}

// ---------------- prep: 3 kernels (zero, deg, norm-with-inline-rsqrt) ----------------
__global__ void k_zero_deg() {
    int i = blockIdx.x * 256 + threadIdx.x;
    if (i < N_NODES) g_deg[i] = 0.f;
}

__global__ void k_deg(const int* __restrict__ col) {
    int e = blockIdx.x * 256 + threadIdx.x;
    if (e < N_EDGES) atomicAdd(&g_deg[col[e]], 1.0f);
}

__global__ void k_norm(const int* __restrict__ row, const int* __restrict__ col) {
    int e = blockIdx.x * 256 + threadIdx.x;
    if (e >= N_EDGES) return;
    float dr = g_deg[row[e]];
    float dc = g_deg[col[e]];
    float ir = (dr > 0.f) ? rsqrtf(dr) : 0.f;
    float ic = (dc > 0.f) ? rsqrtf(dc) : 0.f;
    g_norm[e] = ir * ic;
}

// ---------------- stacked GEMM: pool[kh*N*out_d + n*out_d + o] = sum_i A[n][i]*W[kh*out_d+o][i]
// BM=128, BN=64, BK=16, TM=8, TN=4, 256 threads. a_off>=0 selects pool as A source.
__global__ void __launch_bounds__(256) k_gemm(const float* __restrict__ Ax,
                                              const float* __restrict__ W,
                                              int a_off, int K, int out_shift) {
    __shared__ float As[16][132];
    __shared__ float Bs[16][68];
    const int tid = threadIdx.x;
    const int n0 = blockIdx.x * 128;
    const int m0 = blockIdx.y * 64;
    const int tx = tid & 15;        // 0..15 -> 4 output cols
    const int ty = tid >> 4;        // 0..15 -> 8 output rows
    const int lr = tid >> 2;        // 0..63 load row
    const int lc = (tid & 3) << 2;  // 0,4,8,12 load k-col

    float acc[8][4] = {};

    for (int k0 = 0; k0 < K; k0 += 16) {
        const int nA0 = n0 + lr;
        const int nA1 = n0 + lr + 64;
        float4 a0 = make_float4(0.f, 0.f, 0.f, 0.f);
        float4 a1 = make_float4(0.f, 0.f, 0.f, 0.f);
        if (a_off >= 0) {
            if (nA0 < N_NODES) a0 = *(const float4*)&g_pool[(size_t)a_off + (size_t)nA0 * K + k0 + lc];
            if (nA1 < N_NODES) a1 = *(const float4*)&g_pool[(size_t)a_off + (size_t)nA1 * K + k0 + lc];
        } else {
            if (nA0 < N_NODES) a0 = *(const float4*)&Ax[(size_t)nA0 * K + k0 + lc];
            if (nA1 < N_NODES) a1 = *(const float4*)&Ax[(size_t)nA1 * K + k0 + lc];
        }
        float4 b = *(const float4*)&W[(size_t)(m0 + lr) * K + k0 + lc];

        As[lc + 0][lr] = a0.x; As[lc + 1][lr] = a0.y; As[lc + 2][lr] = a0.z; As[lc + 3][lr] = a0.w;
        As[lc + 0][lr + 64] = a1.x; As[lc + 1][lr + 64] = a1.y; As[lc + 2][lr + 64] = a1.z; As[lc + 3][lr + 64] = a1.w;
        Bs[lc + 0][lr] = b.x; Bs[lc + 1][lr] = b.y; Bs[lc + 2][lr] = b.z; Bs[lc + 3][lr] = b.w;
        __syncthreads();

#pragma unroll
        for (int kk = 0; kk < 16; kk++) {
            float4 aa0 = *(float4*)&As[kk][ty * 8];
            float4 aa1 = *(float4*)&As[kk][ty * 8 + 4];
            float4 bb  = *(float4*)&Bs[kk][tx * 4];
            float av[8] = {aa0.x, aa0.y, aa0.z, aa0.w, aa1.x, aa1.y, aa1.z, aa1.w};
            float bv[4] = {bb.x, bb.y, bb.z, bb.w};
#pragma unroll
            for (int i = 0; i < 8; i++)
#pragma unroll
                for (int j = 0; j < 4; j++)
                    acc[i][j] = fmaf(av[i], bv[j], acc[i][j]);
        }
        __syncthreads();
    }

    const int out_d = 1 << out_shift;
#pragma unroll
    for (int i = 0; i < 8; i++) {
        const int n = n0 + ty * 8 + i;
        if (n >= N_NODES) continue;
#pragma unroll
        for (int j = 0; j < 4; j++) {
            const int m = m0 + tx * 4 + j;
            const int kh = m >> out_shift;
            const int o = m & (out_d - 1);
            g_pool[(size_t)kh * N_NODES * out_d + (size_t)n * out_d + o] = acc[i][j];
        }
    }
}

// ---------------- SpMM hop: pool[dst + col*d] += norm * pool[src + row*d]
// LANES threads per edge, each handles a float4 via ONE red.global.add.v4.f32
template <int LANES>
__global__ void __launch_bounds__(256) k_spmm(int src_off, int dst_off,
                                              const int* __restrict__ row,
                                              const int* __restrict__ col) {
    const long long t = (long long)blockIdx.x * 256 + threadIdx.x;
    const int e = (int)(t / LANES);
    const int l = (int)(t % LANES);
    if (e >= N_EDGES) return;
    const int d = LANES * 4;
    const int r = row[e];
    const int c = col[e];
    const float w = g_norm[e];
    const float4 v = *(const float4*)&g_pool[(size_t)src_off + (size_t)r * d + l * 4];
    float* p = &g_pool[(size_t)dst_off + (size_t)c * d + l * 4];
    asm volatile("red.global.add.v4.f32 [%0], {%1, %2, %3, %4};"
                 :: "l"(p), "f"(v.x * w), "f"(v.y * w), "f"(v.z * w), "f"(v.w * w)
                 : "memory");
}

// ---------------- finalize: bias (+ELU) + exact-JAX dropout; pool -> pool ----------------
__global__ void k_fin_drop(const float* __restrict__ b, int z_off, int h_off,
                           int total, int dmask, unsigned k0, unsigned k1, int do_elu) {
    int i = blockIdx.x * 256 + threadIdx.x;
    if (i >= total) return;
    unsigned x0 = 0u, x1 = (unsigned)i;   // partitionable random_bits: counter (hi,lo)=(0,i)
    threefry2x32(k0, k1, x0, x1);
    const unsigned bits = x0 ^ x1;        // 32-bit output: lane0 ^ lane1
    float v = g_pool[(size_t)z_off + i] + b[i & dmask];
    if (do_elu) v = (v > 0.f) ? v : expm1f(v);
    // keep iff uniform < 0.5 iff top bit clear; kept values scaled by 1/(1-p)=2
    g_pool[(size_t)h_off + i] = (bits & 0x80000000u) ? 0.f : v * 2.0f;
}

__global__ void k_fin_bias(const float* __restrict__ b, float* __restrict__ out,
                           int total, int dmask) {
    int i = blockIdx.x * 256 + threadIdx.x;
    if (i >= total) return;
    out[i] = g_pool[i] + b[i & dmask];
}

// ---------------- driver ----------------
static inline int cdiv(long long a, long long b) { return (int)((a + b - 1) / b); }

extern "C" void kernel_launch(void* const* d_in, const int* in_sizes, int n_in,
                              void* d_out, int out_size) {
    const float* x   = (const float*)d_in[0];
    const int*   ei  = (const int*)d_in[1];      // JAX default: int32 (no x64)
    const float* W1  = (const float*)d_in[2];
    const float* b1  = (const float*)d_in[3];
    const float* W2  = (const float*)d_in[4];
    const float* b2  = (const float*)d_in[5];
    const float* W3  = (const float*)d_in[6];
    const float* b3  = (const float*)d_in[7];
    float*       out = (float*)d_out;

    const int* row = ei;
    const int* col = ei + N_EDGES;

    // dropout keys: dk1, dk2 = split(key(42)); foldlike split -> threefry(key,(0,i)), both lanes
    unsigned dk1a = 0u, dk1b = 0u; threefry2x32(0u, 42u, dk1a, dk1b);   // counter (0,0)
    unsigned dk2a = 0u, dk2b = 1u; threefry2x32(0u, 42u, dk2a, dk2b);   // counter (0,1)

    const int H_OFF = 3 * SLAB;     // h lives in slab 3 (free after the last Horner hop)

    // --- normalization (3 launches; next launch = heavy GEMM for ncu capture slot) ---
    k_zero_deg<<<cdiv(N_NODES, 256), 256>>>();
    k_deg<<<cdiv(N_EDGES, 256), 256>>>(col);
    k_norm<<<cdiv(N_EDGES, 256), 256>>>(row, col);

    // --- Layer 1: in=128, out=128 (shift 7), M=512. z0..z3 = slabs 0..3 (dim 128).
    //     Horner: z2+=A z3; z1+=A z2; z0+=A z1. Then h1 = drop(z0+b1) -> slab 3.
    {
        dim3 g(cdiv(N_NODES, 128), 512 / 64);
        k_gemm<<<g, 256>>>(x, W1, -1, 128, 7);
        const int S = SLAB;
        const long long tot = (long long)N_EDGES * 32;
        k_spmm<32><<<cdiv(tot, 256), 256>>>(3 * S, 2 * S, row, col);
        k_spmm<32><<<cdiv(tot, 256), 256>>>(2 * S, 1 * S, row, col);
        k_spmm<32><<<cdiv(tot, 256), 256>>>(1 * S, 0 * S, row, col);
        k_fin_drop<<<cdiv(N_NODES * 128, 256), 256>>>(b1, 0, H_OFF, N_NODES * 128, 127, dk1a, dk1b, 0);
    }

    // --- Layer 2: in=128 (A at H_OFF), out=64 (shift 6), M=256. z'0..z'3 at 0..3*S (dim 64).
    //     Then h2 = drop(elu(z'0+b2)) -> H_OFF (h1 dead after GEMM).
    {
        dim3 g(cdiv(N_NODES, 128), 256 / 64);
        k_gemm<<<g, 256>>>(nullptr, W2, H_OFF, 128, 6);
        const int S = N_NODES * 64;
        const long long tot = (long long)N_EDGES * 16;
        k_spmm<16><<<cdiv(tot, 256), 256>>>(3 * S, 2 * S, row, col);
        k_spmm<16><<<cdiv(tot, 256), 256>>>(2 * S, 1 * S, row, col);
        k_spmm<16><<<cdiv(tot, 256), 256>>>(1 * S, 0 * S, row, col);
        k_fin_drop<<<cdiv(N_NODES * 64, 256), 256>>>(b2, 0, H_OFF, N_NODES * 64, 63, dk2a, dk2b, 1);
    }

    // --- Layer 3: in=64 (A at H_OFF), out=16 (shift 4), M=64. z''0..z''3 at 0..3*S (dim 16). ---
    {
        dim3 g(cdiv(N_NODES, 128), 64 / 64);
        k_gemm<<<g, 256>>>(nullptr, W3, H_OFF, 64, 4);
        const int S = N_NODES * 16;
        const long long tot = (long long)N_EDGES * 4;
        k_spmm<4><<<cdiv(tot, 256), 256>>>(3 * S, 2 * S, row, col);
        k_spmm<4><<<cdiv(tot, 256), 256>>>(2 * S, 1 * S, row, col);
        k_spmm<4><<<cdiv(tot, 256), 256>>>(1 * S, 0 * S, row, col);
        k_fin_bias<<<cdiv(N_NODES * 16, 256), 256>>>(b3, out, N_NODES * 16, 15);
    }
}

// round 9
// speedup vs baseline: 1.9427x; 1.0943x over previous
#include <cuda_runtime.h>
#include <cstdint>
#include <math.h>

#define N_NODES 100000
#define N_EDGES 1600000
#define SLAB 12800000               // N_NODES * 128 elements

// ---------------- static scratch ≈ 225MB (<256MB cliff) ----------------
__device__ __align__(16) float g_pool[(size_t)4 * SLAB];   // 204.8MB
__device__ __align__(16) float g_norm[N_EDGES];            // 6.4MB (edge order)
__device__ __align__(16) float g_pnorm[N_EDGES];           // 6.4MB (CSR order)
__device__ __align__(16) int   g_prow[N_EDGES];            // 6.4MB (CSR src ids)
__device__ __align__(16) int   g_ideg[N_NODES];
__device__ __align__(16) int   g_cnt[N_NODES];
__device__ __align__(16) int   g_off[N_NODES + 1];

// ---------------- Threefry-2x32-20 (exact JAX semantics) ----------------
__host__ __device__ __forceinline__ unsigned rotl32(unsigned x, int r) {
    return (x << r) | (x >> (32 - r));
}
__host__ __device__ __forceinline__ void threefry2x32(unsigned k0, unsigned k1,
                                                      unsigned& x0, unsigned& x1) {
    const unsigned ks2 = k0 ^ k1 ^ 0x1BD11BDAu;
    x0 += k0; x1 += k1;
#define TF_RND(r) { x0 += x1; x1 = rotl32(x1, (r)); x1 ^= x0; }
    TF_RND(13) TF_RND(15) TF_RND(26) TF_RND(6)
    x0 += k1;  x1 += ks2 + 1u;
    TF_RND(17) TF_RND(29) TF_RND(16) TF_RND(24)
    x0 += ks2; x1 += k0 + 2u;
    TF_RND(13) TF_RND(15) TF_RND(26) TF_RND(6)
    x0 += k0;  x1 += k1 + 3u;
    TF_RND(17) TF_RND(29) TF_RND(16) TF_RND(24)
    x0 += k1;  x1 += ks2 + 4u;
    TF_RND(13) TF_RND(15) TF_RND(26) TF_RND(6)
    x0 += ks2; x1 += k0 + 5u;
#undef TF_RND
}

// ---------------- prep: degree, norm, CSR build ----------------
__global__ void k_zero() {
    int i = blockIdx.x * 256 + threadIdx.x;
    if (i < N_NODES) { g_ideg[i] = 0; g_cnt[i] = 0; }
}
__global__ void k_deg(const int* __restrict__ col) {
    int e = blockIdx.x * 256 + threadIdx.x;
    if (e < N_EDGES) atomicAdd(&g_ideg[col[e]], 1);
}
__global__ void k_norm(const int* __restrict__ row, const int* __restrict__ col) {
    int e = blockIdx.x * 256 + threadIdx.x;
    if (e >= N_EDGES) return;
    int dr = g_ideg[row[e]];
    int dc = g_ideg[col[e]];
    float ir = (dr > 0) ? rsqrtf((float)dr) : 0.f;
    float ic = (dc > 0) ? rsqrtf((float)dc) : 0.f;
    g_norm[e] = ir * ic;
}
// single-block exclusive scan of g_ideg -> g_off
__global__ void __launch_bounds__(1024) k_scan() {
    __shared__ int sh[1024];
    __shared__ int carry;
    if (threadIdx.x == 0) carry = 0;
    __syncthreads();
    for (int base = 0; base < N_NODES; base += 1024) {
        int i = base + (int)threadIdx.x;
        int v = (i < N_NODES) ? g_ideg[i] : 0;
        sh[threadIdx.x] = v;
        __syncthreads();
        for (int off = 1; off < 1024; off <<= 1) {
            int t = (threadIdx.x >= off) ? sh[threadIdx.x - off] : 0;
            __syncthreads();
            sh[threadIdx.x] += t;
            __syncthreads();
        }
        if (i < N_NODES) g_off[i] = carry + sh[threadIdx.x] - v;  // exclusive
        __syncthreads();
        if (threadIdx.x == 1023) carry += sh[1023];
        __syncthreads();
    }
    if (threadIdx.x == 0) g_off[N_NODES] = carry;
}
__global__ void k_scatter(const int* __restrict__ row, const int* __restrict__ col) {
    int e = blockIdx.x * 256 + threadIdx.x;
    if (e >= N_EDGES) return;
    int c = col[e];
    int pos = g_off[c] + atomicAdd(&g_cnt[c], 1);
    g_prow[pos] = row[e];
    g_pnorm[pos] = g_norm[e];
}

// ---------------- stacked GEMM 128x128 tile, 8x8/thread ----------------
// pool[(m>>sh)*N*out_d + n*out_d + (m&mask)] = sum_k A[n][k] * W[m][k]
__global__ void __launch_bounds__(256) k_gemm(const float* __restrict__ Ax,
                                              const float* __restrict__ W,
                                              int a_off, int K, int out_shift, int M_total) {
    __shared__ float As[16][132];
    __shared__ float Bs[16][132];
    const int tid = threadIdx.x;
    const int n0 = blockIdx.x * 128;
    const int m0 = blockIdx.y * 128;
    const int tx = tid & 15;        // -> 8 output cols
    const int ty = tid >> 4;        // -> 8 output rows
    const int lr = tid >> 1;        // 0..127 load row
    const int lc = (tid & 1) * 8;   // 0 or 8 (two float4)

    float acc[8][8] = {};

    for (int k0 = 0; k0 < K; k0 += 16) {
        const int nA = n0 + lr;
        float4 a0 = make_float4(0.f, 0.f, 0.f, 0.f), a1 = a0;
        if (nA < N_NODES) {
            const float* src = (a_off >= 0) ? (g_pool + a_off) : Ax;
            a0 = *(const float4*)&src[(size_t)nA * K + k0 + lc];
            a1 = *(const float4*)&src[(size_t)nA * K + k0 + lc + 4];
        }
        const int mB = m0 + lr;
        float4 b0 = make_float4(0.f, 0.f, 0.f, 0.f), b1 = b0;
        if (mB < M_total) {
            b0 = *(const float4*)&W[(size_t)mB * K + k0 + lc];
            b1 = *(const float4*)&W[(size_t)mB * K + k0 + lc + 4];
        }
        As[lc + 0][lr] = a0.x; As[lc + 1][lr] = a0.y; As[lc + 2][lr] = a0.z; As[lc + 3][lr] = a0.w;
        As[lc + 4][lr] = a1.x; As[lc + 5][lr] = a1.y; As[lc + 6][lr] = a1.z; As[lc + 7][lr] = a1.w;
        Bs[lc + 0][lr] = b0.x; Bs[lc + 1][lr] = b0.y; Bs[lc + 2][lr] = b0.z; Bs[lc + 3][lr] = b0.w;
        Bs[lc + 4][lr] = b1.x; Bs[lc + 5][lr] = b1.y; Bs[lc + 6][lr] = b1.z; Bs[lc + 7][lr] = b1.w;
        __syncthreads();

#pragma unroll
        for (int kk = 0; kk < 16; kk++) {
            float4 aa0 = *(float4*)&As[kk][ty * 8];
            float4 aa1 = *(float4*)&As[kk][ty * 8 + 4];
            float4 bb0 = *(float4*)&Bs[kk][tx * 8];
            float4 bb1 = *(float4*)&Bs[kk][tx * 8 + 4];
            float av[8] = {aa0.x, aa0.y, aa0.z, aa0.w, aa1.x, aa1.y, aa1.z, aa1.w};
            float bv[8] = {bb0.x, bb0.y, bb0.z, bb0.w, bb1.x, bb1.y, bb1.z, bb1.w};
#pragma unroll
            for (int i = 0; i < 8; i++)
#pragma unroll
                for (int j = 0; j < 8; j++)
                    acc[i][j] = fmaf(av[i], bv[j], acc[i][j]);
        }
        __syncthreads();
    }

    const int out_d = 1 << out_shift;
#pragma unroll
    for (int i = 0; i < 8; i++) {
        const int n = n0 + ty * 8 + i;
        if (n >= N_NODES) continue;
#pragma unroll
        for (int j = 0; j < 8; j++) {
            const int m = m0 + tx * 8 + j;
            if (m >= M_total) continue;
            const int kh = m >> out_shift;
            const int o = m & (out_d - 1);
            g_pool[(size_t)kh * N_NODES * out_d + (size_t)n * out_d + o] = acc[i][j];
        }
    }
}

// ---------------- CSR gather hop: dst[n] += sum_{e in in(n)} w_e * src[prow[e]]
// SUB lanes per node, each lane owns a float4 (d = SUB*4)
template <int SUB>
__global__ void __launch_bounds__(256) k_gather(int src_off, int dst_off) {
    const int g = blockIdx.x * 256 + threadIdx.x;
    const int node = g / SUB;
    const int lane = g % SUB;
    if (node >= N_NODES) return;
    const int d = SUB * 4;
    const int start = g_off[node];
    const int end = g_off[node + 1];
    const size_t doff = (size_t)dst_off + (size_t)node * d + lane * 4;
    float4 acc = *(float4*)&g_pool[doff];
    for (int i = start; i < end; i++) {
        const int r = g_prow[i];
        const float w = g_pnorm[i];
        const float4 v = *(const float4*)&g_pool[(size_t)src_off + (size_t)r * d + lane * 4];
        acc.x = fmaf(w, v.x, acc.x);
        acc.y = fmaf(w, v.y, acc.y);
        acc.z = fmaf(w, v.z, acc.z);
        acc.w = fmaf(w, v.w, acc.w);
    }
    *(float4*)&g_pool[doff] = acc;
}

// ---------------- finalize: bias (+ELU) + exact-JAX dropout; pool -> pool ----------------
__global__ void k_fin_drop(const float* __restrict__ b, int z_off, int h_off,
                           int total, int dmask, unsigned k0, unsigned k1, int do_elu) {
    int i = blockIdx.x * 256 + threadIdx.x;
    if (i >= total) return;
    unsigned x0 = 0u, x1 = (unsigned)i;
    threefry2x32(k0, k1, x0, x1);
    const unsigned bits = x0 ^ x1;
    float v = g_pool[(size_t)z_off + i] + b[i & dmask];
    if (do_elu) v = (v > 0.f) ? v : expm1f(v);
    g_pool[(size_t)h_off + i] = (bits & 0x80000000u) ? 0.f : v * 2.0f;
}

__global__ void k_fin_bias(const float* __restrict__ b, float* __restrict__ out,
                           int total, int dmask) {
    int i = blockIdx.x * 256 + threadIdx.x;
    if (i >= total) return;
    out[i] = g_pool[i] + b[i & dmask];
}

// ---------------- driver ----------------
static inline int cdiv(long long a, long long b) { return (int)((a + b - 1) / b); }

extern "C" void kernel_launch(void* const* d_in, const int* in_sizes, int n_in,
                              void* d_out, int out_size) {
    const float* x   = (const float*)d_in[0];
    const int*   ei  = (const int*)d_in[1];
    const float* W1  = (const float*)d_in[2];
    const float* b1  = (const float*)d_in[3];
    const float* W2  = (const float*)d_in[4];
    const float* b2  = (const float*)d_in[5];
    const float* W3  = (const float*)d_in[6];
    const float* b3  = (const float*)d_in[7];
    float*       out = (float*)d_out;

    const int* row = ei;
    const int* col = ei + N_EDGES;

    unsigned dk1a = 0u, dk1b = 0u; threefry2x32(0u, 42u, dk1a, dk1b);   // counter (0,0)
    unsigned dk2a = 0u, dk2b = 1u; threefry2x32(0u, 42u, dk2a, dk2b);   // counter (0,1)

    const int H_OFF = 3 * SLAB;

    // --- prep: degrees, norms, CSR ---
    k_zero<<<cdiv(N_NODES, 256), 256>>>();
    k_deg<<<cdiv(N_EDGES, 256), 256>>>(col);
    k_norm<<<cdiv(N_EDGES, 256), 256>>>(row, col);
    k_scan<<<1, 1024>>>();
    k_scatter<<<cdiv(N_EDGES, 256), 256>>>(row, col);

    // --- Layer 1: in=128, out=128 (shift 7), M=512. z0..z3 = slabs 0..3.
    //     Horner: z2+=A z3; z1+=A z2; z0+=A z1. Then h1 = drop(z0+b1) -> slab 3.
    {
        dim3 g(cdiv(N_NODES, 128), 4);
        k_gemm<<<g, 256>>>(x, W1, -1, 128, 7, 512);
        const int S = SLAB;
        const int gg = cdiv((long long)N_NODES * 32, 256);
        k_gather<32><<<gg, 256>>>(3 * S, 2 * S);
        k_gather<32><<<gg, 256>>>(2 * S, 1 * S);
        k_gather<32><<<gg, 256>>>(1 * S, 0 * S);
        k_fin_drop<<<cdiv(N_NODES * 128, 256), 256>>>(b1, 0, H_OFF, N_NODES * 128, 127, dk1a, dk1b, 0);
    }

    // --- Layer 2: in=128 (A at H_OFF), out=64 (shift 6), M=256 ---
    {
        dim3 g(cdiv(N_NODES, 128), 2);
        k_gemm<<<g, 256>>>(nullptr, W2, H_OFF, 128, 6, 256);
        const int S = N_NODES * 64;
        const int gg = cdiv((long long)N_NODES * 16, 256);
        k_gather<16><<<gg, 256>>>(3 * S, 2 * S);
        k_gather<16><<<gg, 256>>>(2 * S, 1 * S);
        k_gather<16><<<gg, 256>>>(1 * S, 0 * S);
        k_fin_drop<<<cdiv(N_NODES * 64, 256), 256>>>(b2, 0, H_OFF, N_NODES * 64, 63, dk2a, dk2b, 1);
    }

    // --- Layer 3: in=64 (A at H_OFF), out=16 (shift 4), M=64 ---
    {
        dim3 g(cdiv(N_NODES, 128), 1);
        k_gemm<<<g, 256>>>(nullptr, W3, H_OFF, 64, 4, 64);
        const int S = N_NODES * 16;
        const int gg = cdiv((long long)N_NODES * 4, 256);
        k_gather<4><<<gg, 256>>>(3 * S, 2 * S);
        k_gather<4><<<gg, 256>>>(2 * S, 1 * S);
        k_gather<4><<<gg, 256>>>(1 * S, 0 * S);
        k_fin_bias<<<cdiv(N_NODES * 16, 256), 256>>>(b3, out, N_NODES * 16, 15);
    }
}

// round 10
// speedup vs baseline: 2.2294x; 1.1475x over previous
#include <cuda_runtime.h>
#include <cstdint>
#include <math.h>

#define N_NODES 100000
#define N_EDGES 1600000
#define SLAB 12800000               // N_NODES * 128 elements
#define SCAN_BLOCKS 98              // ceil(100000 / 1024)

// ---------------- static scratch ≈ 218MB (<256MB cliff) ----------------
__device__ __align__(16) float g_pool[(size_t)4 * SLAB];   // 204.8MB
__device__ __align__(16) float g_pnorm[N_EDGES];           // 6.4MB (CSR order)
__device__ __align__(16) int   g_prow[N_EDGES];            // 6.4MB (CSR src ids)
__device__ __align__(16) int   g_ideg[N_NODES];
__device__ __align__(16) int   g_cnt[N_NODES];
__device__ __align__(16) int   g_off[N_NODES + 1];
__device__ __align__(16) int   g_bsum[SCAN_BLOCKS];

// ---------------- Threefry-2x32-20 (exact JAX semantics) ----------------
__host__ __device__ __forceinline__ unsigned rotl32(unsigned x, int r) {
    return (x << r) | (x >> (32 - r));
}
__host__ __device__ __forceinline__ void threefry2x32(unsigned k0, unsigned k1,
                                                      unsigned& x0, unsigned& x1) {
    const unsigned ks2 = k0 ^ k1 ^ 0x1BD11BDAu;
    x0 += k0; x1 += k1;
#define TF_RND(r) { x0 += x1; x1 = rotl32(x1, (r)); x1 ^= x0; }
    TF_RND(13) TF_RND(15) TF_RND(26) TF_RND(6)
    x0 += k1;  x1 += ks2 + 1u;
    TF_RND(17) TF_RND(29) TF_RND(16) TF_RND(24)
    x0 += ks2; x1 += k0 + 2u;
    TF_RND(13) TF_RND(15) TF_RND(26) TF_RND(6)
    x0 += k0;  x1 += k1 + 3u;
    TF_RND(17) TF_RND(29) TF_RND(16) TF_RND(24)
    x0 += k1;  x1 += ks2 + 4u;
    TF_RND(13) TF_RND(15) TF_RND(26) TF_RND(6)
    x0 += ks2; x1 += k0 + 5u;
#undef TF_RND
}

// ---------------- prep: degree + parallel CSR build ----------------
__global__ void k_zero() {
    int i = blockIdx.x * 256 + threadIdx.x;
    if (i < N_NODES) { g_ideg[i] = 0; g_cnt[i] = 0; }
}
__global__ void k_deg(const int* __restrict__ col) {
    int e = blockIdx.x * 256 + threadIdx.x;
    if (e < N_EDGES) atomicAdd(&g_ideg[col[e]], 1);
}
// phase A: per-block exclusive scan (1024 elems/block) + block sums
__global__ void __launch_bounds__(1024) k_scanA() {
    __shared__ int sh[1024];
    const int i = blockIdx.x * 1024 + threadIdx.x;
    int v = (i < N_NODES) ? g_ideg[i] : 0;
    sh[threadIdx.x] = v;
    __syncthreads();
#pragma unroll
    for (int off = 1; off < 1024; off <<= 1) {
        int t = (threadIdx.x >= off) ? sh[threadIdx.x - off] : 0;
        __syncthreads();
        sh[threadIdx.x] += t;
        __syncthreads();
    }
    if (i < N_NODES) g_off[i] = sh[threadIdx.x] - v;   // local exclusive
    if (threadIdx.x == 1023) g_bsum[blockIdx.x] = sh[1023];
}
// phase B: exclusive scan of the 98 block sums (one tiny block)
__global__ void __launch_bounds__(128) k_scanB() {
    __shared__ int sh[128];
    int v = (threadIdx.x < SCAN_BLOCKS) ? g_bsum[threadIdx.x] : 0;
    sh[threadIdx.x] = v;
    __syncthreads();
#pragma unroll
    for (int off = 1; off < 128; off <<= 1) {
        int t = (threadIdx.x >= off) ? sh[threadIdx.x - off] : 0;
        __syncthreads();
        sh[threadIdx.x] += t;
        __syncthreads();
    }
    if (threadIdx.x < SCAN_BLOCKS) g_bsum[threadIdx.x] = sh[threadIdx.x] - v;
}
// phase C: add block prefix; all degrees sum to N_EDGES so off[N] is constant
__global__ void __launch_bounds__(1024) k_scanC() {
    const int i = blockIdx.x * 1024 + threadIdx.x;
    if (i < N_NODES) g_off[i] += g_bsum[blockIdx.x];
    if (i == 0) g_off[N_NODES] = N_EDGES;
}
// scatter-permute edges into CSR order; norm computed inline from degrees
__global__ void k_scatter(const int* __restrict__ row, const int* __restrict__ col) {
    int e = blockIdx.x * 256 + threadIdx.x;
    if (e >= N_EDGES) return;
    const int r = row[e];
    const int c = col[e];
    const int pos = g_off[c] + atomicAdd(&g_cnt[c], 1);
    const int dr = g_ideg[r];
    const int dc = g_ideg[c];
    const float ir = (dr > 0) ? rsqrtf((float)dr) : 0.f;
    const float ic = (dc > 0) ? rsqrtf((float)dc) : 0.f;
    g_prow[pos] = r;
    g_pnorm[pos] = ir * ic;
}

// ---------------- stacked GEMM 128x128 tile, 8x8/thread ----------------
// pool[(m>>sh)*N*out_d + n*out_d + (m&mask)] = sum_k A[n][k] * W[m][k]
__global__ void __launch_bounds__(256) k_gemm(const float* __restrict__ Ax,
                                              const float* __restrict__ W,
                                              int a_off, int K, int out_shift, int M_total) {
    __shared__ float As[16][132];
    __shared__ float Bs[16][132];
    const int tid = threadIdx.x;
    const int n0 = blockIdx.x * 128;
    const int m0 = blockIdx.y * 128;
    const int tx = tid & 15;        // -> 8 output cols
    const int ty = tid >> 4;        // -> 8 output rows
    const int lr = tid >> 1;        // 0..127 load row
    const int lc = (tid & 1) * 8;   // 0 or 8 (two float4)

    float acc[8][8] = {};

    for (int k0 = 0; k0 < K; k0 += 16) {
        const int nA = n0 + lr;
        float4 a0 = make_float4(0.f, 0.f, 0.f, 0.f), a1 = a0;
        if (nA < N_NODES) {
            const float* src = (a_off >= 0) ? (g_pool + a_off) : Ax;
            a0 = *(const float4*)&src[(size_t)nA * K + k0 + lc];
            a1 = *(const float4*)&src[(size_t)nA * K + k0 + lc + 4];
        }
        const int mB = m0 + lr;
        float4 b0 = make_float4(0.f, 0.f, 0.f, 0.f), b1 = b0;
        if (mB < M_total) {
            b0 = *(const float4*)&W[(size_t)mB * K + k0 + lc];
            b1 = *(const float4*)&W[(size_t)mB * K + k0 + lc + 4];
        }
        As[lc + 0][lr] = a0.x; As[lc + 1][lr] = a0.y; As[lc + 2][lr] = a0.z; As[lc + 3][lr] = a0.w;
        As[lc + 4][lr] = a1.x; As[lc + 5][lr] = a1.y; As[lc + 6][lr] = a1.z; As[lc + 7][lr] = a1.w;
        Bs[lc + 0][lr] = b0.x; Bs[lc + 1][lr] = b0.y; Bs[lc + 2][lr] = b0.z; Bs[lc + 3][lr] = b0.w;
        Bs[lc + 4][lr] = b1.x; Bs[lc + 5][lr] = b1.y; Bs[lc + 6][lr] = b1.z; Bs[lc + 7][lr] = b1.w;
        __syncthreads();

#pragma unroll
        for (int kk = 0; kk < 16; kk++) {
            float4 aa0 = *(float4*)&As[kk][ty * 8];
            float4 aa1 = *(float4*)&As[kk][ty * 8 + 4];
            float4 bb0 = *(float4*)&Bs[kk][tx * 8];
            float4 bb1 = *(float4*)&Bs[kk][tx * 8 + 4];
            float av[8] = {aa0.x, aa0.y, aa0.z, aa0.w, aa1.x, aa1.y, aa1.z, aa1.w};
            float bv[8] = {bb0.x, bb0.y, bb0.z, bb0.w, bb1.x, bb1.y, bb1.z, bb1.w};
#pragma unroll
            for (int i = 0; i < 8; i++)
#pragma unroll
                for (int j = 0; j < 8; j++)
                    acc[i][j] = fmaf(av[i], bv[j], acc[i][j]);
        }
        __syncthreads();
    }

    const int out_d = 1 << out_shift;
#pragma unroll
    for (int i = 0; i < 8; i++) {
        const int n = n0 + ty * 8 + i;
        if (n >= N_NODES) continue;
#pragma unroll
        for (int j = 0; j < 8; j++) {
            const int m = m0 + tx * 8 + j;
            if (m >= M_total) continue;
            const int kh = m >> out_shift;
            const int o = m & (out_d - 1);
            g_pool[(size_t)kh * N_NODES * out_d + (size_t)n * out_d + o] = acc[i][j];
        }
    }
}

// ---------------- CSR gather hop: dst[n] += sum_{e in in(n)} w_e * src[prow[e]]
// SUB lanes per node, each lane owns a float4 (d = SUB*4)
template <int SUB>
__global__ void __launch_bounds__(256) k_gather(int src_off, int dst_off) {
    const int g = blockIdx.x * 256 + threadIdx.x;
    const int node = g / SUB;
    const int lane = g % SUB;
    if (node >= N_NODES) return;
    const int d = SUB * 4;
    const int start = g_off[node];
    const int end = g_off[node + 1];
    const size_t doff = (size_t)dst_off + (size_t)node * d + lane * 4;
    float4 acc = *(float4*)&g_pool[doff];
    for (int i = start; i < end; i++) {
        const int r = g_prow[i];
        const float w = g_pnorm[i];
        const float4 v = *(const float4*)&g_pool[(size_t)src_off + (size_t)r * d + lane * 4];
        acc.x = fmaf(w, v.x, acc.x);
        acc.y = fmaf(w, v.y, acc.y);
        acc.z = fmaf(w, v.z, acc.z);
        acc.w = fmaf(w, v.w, acc.w);
    }
    *(float4*)&g_pool[doff] = acc;
}

// ---------------- finalize: bias (+ELU) + exact-JAX dropout; pool -> pool ----------------
__global__ void k_fin_drop(const float* __restrict__ b, int z_off, int h_off,
                           int total, int dmask, unsigned k0, unsigned k1, int do_elu) {
    int i = blockIdx.x * 256 + threadIdx.x;
    if (i >= total) return;
    unsigned x0 = 0u, x1 = (unsigned)i;
    threefry2x32(k0, k1, x0, x1);
    const unsigned bits = x0 ^ x1;
    float v = g_pool[(size_t)z_off + i] + b[i & dmask];
    if (do_elu) v = (v > 0.f) ? v : expm1f(v);
    g_pool[(size_t)h_off + i] = (bits & 0x80000000u) ? 0.f : v * 2.0f;
}

__global__ void k_fin_bias(const float* __restrict__ b, float* __restrict__ out,
                           int total, int dmask) {
    int i = blockIdx.x * 256 + threadIdx.x;
    if (i >= total) return;
    out[i] = g_pool[i] + b[i & dmask];
}

// ---------------- driver ----------------
static inline int cdiv(long long a, long long b) { return (int)((a + b - 1) / b); }

extern "C" void kernel_launch(void* const* d_in, const int* in_sizes, int n_in,
                              void* d_out, int out_size) {
    const float* x   = (const float*)d_in[0];
    const int*   ei  = (const int*)d_in[1];
    const float* W1  = (const float*)d_in[2];
    const float* b1  = (const float*)d_in[3];
    const float* W2  = (const float*)d_in[4];
    const float* b2  = (const float*)d_in[5];
    const float* W3  = (const float*)d_in[6];
    const float* b3  = (const float*)d_in[7];
    float*       out = (float*)d_out;

    const int* row = ei;
    const int* col = ei + N_EDGES;

    unsigned dk1a = 0u, dk1b = 0u; threefry2x32(0u, 42u, dk1a, dk1b);   // counter (0,0)
    unsigned dk2a = 0u, dk2b = 1u; threefry2x32(0u, 42u, dk2a, dk2b);   // counter (0,1)

    const int H_OFF = 3 * SLAB;

    // --- prep: degrees + parallel CSR build (scan in 3 fast phases) ---
    k_zero<<<cdiv(N_NODES, 256), 256>>>();
    k_deg<<<cdiv(N_EDGES, 256), 256>>>(col);
    k_scanA<<<SCAN_BLOCKS, 1024>>>();
    k_scanB<<<1, 128>>>();
    k_scanC<<<SCAN_BLOCKS, 1024>>>();
    k_scatter<<<cdiv(N_EDGES, 256), 256>>>(row, col);

    // --- Layer 1: in=128, out=128 (shift 7), M=512. z0..z3 = slabs 0..3.
    //     Horner: z2+=A z3; z1+=A z2; z0+=A z1. Then h1 = drop(z0+b1) -> slab 3.
    {
        dim3 g(cdiv(N_NODES, 128), 4);
        k_gemm<<<g, 256>>>(x, W1, -1, 128, 7, 512);
        const int S = SLAB;
        const int gg = cdiv((long long)N_NODES * 32, 256);
        k_gather<32><<<gg, 256>>>(3 * S, 2 * S);
        k_gather<32><<<gg, 256>>>(2 * S, 1 * S);
        k_gather<32><<<gg, 256>>>(1 * S, 0 * S);
        k_fin_drop<<<cdiv(N_NODES * 128, 256), 256>>>(b1, 0, H_OFF, N_NODES * 128, 127, dk1a, dk1b, 0);
    }

    // --- Layer 2: in=128 (A at H_OFF), out=64 (shift 6), M=256 ---
    {
        dim3 g(cdiv(N_NODES, 128), 2);
        k_gemm<<<g, 256>>>(nullptr, W2, H_OFF, 128, 6, 256);
        const int S = N_NODES * 64;
        const int gg = cdiv((long long)N_NODES * 16, 256);
        k_gather<16><<<gg, 256>>>(3 * S, 2 * S);
        k_gather<16><<<gg, 256>>>(2 * S, 1 * S);
        k_gather<16><<<gg, 256>>>(1 * S, 0 * S);
        k_fin_drop<<<cdiv(N_NODES * 64, 256), 256>>>(b2, 0, H_OFF, N_NODES * 64, 63, dk2a, dk2b, 1);
    }

    // --- Layer 3: in=64 (A at H_OFF), out=16 (shift 4), M=64 ---
    {
        dim3 g(cdiv(N_NODES, 128), 1);
        k_gemm<<<g, 256>>>(nullptr, W3, H_OFF, 64, 4, 64);
        const int S = N_NODES * 16;
        const int gg = cdiv((long long)N_NODES * 4, 256);
        k_gather<4><<<gg, 256>>>(3 * S, 2 * S);
        k_gather<4><<<gg, 256>>>(2 * S, 1 * S);
        k_gather<4><<<gg, 256>>>(1 * S, 0 * S);
        k_fin_bias<<<cdiv(N_NODES * 16, 256), 256>>>(b3, out, N_NODES * 16, 15);
    }
}